// round 5
// baseline (speedup 1.0000x reference)
#include <cuda_runtime.h>
#include <math.h>

#define EMB 256
#define VOCAB 50000
#define ROWS_OUT 101
#define BN_EPS 1e-5f
#define NY 8
#define NXT 196                       // x-tiles of 256 vocab
#define NLSTM 8
#define GRID_FUSED (NLSTM + NXT * NY) // 1576, multiple of 8

// ---------------- packed f32x2 helpers ----------------
#define FMA2(acc, a, b) \
    asm("fma.rn.f32x2 %0, %1, %2, %0;" : "+l"(acc) : "l"(a), "l"(b))
#define ADD2(acc, b) \
    asm("add.rn.f32x2 %0, %0, %1;" : "+l"(acc) : "l"(b))
#define UNPACK64(lo, hi, v) do { unsigned _ulo, _uhi; \
    asm("mov.b64 {%0, %1}, %2;" : "=r"(_ulo), "=r"(_uhi) : "l"(v)); \
    lo = __uint_as_float(_ulo); hi = __uint_as_float(_uhi); } while (0)
#define PACK64(d, lo, hi) do { unsigned _a = __float_as_uint(lo), _b = __float_as_uint(hi); \
    asm("mov.b64 %0, {%1, %2};" : "=l"(d) : "r"(_a), "r"(_b)); } while (0)
#define DUP2(d, f) do { unsigned _u = __float_as_uint(f); \
    asm("mov.b64 %0, {%1, %1};" : "=l"(d) : "r"(_u)); } while (0)

// ---------------- device scratch ----------------
__device__ float g_wsum[1024 * EMB];
__device__ float g_bsum[1024];
__device__ float g_WlinT[361 * EMB];
__device__ float g_feat[EMB];
__device__ float g_H[ROWS_OUT * EMB];
__device__ int g_flag[NY];

// ---------------- K0 ----------------
__global__ void k0_precompute(const float* __restrict__ Wih,
                              const float* __restrict__ Whh,
                              const float* __restrict__ bih,
                              const float* __restrict__ bhh,
                              const float* __restrict__ Wlin) {
    int i = blockIdx.x * blockDim.x + threadIdx.x;
    int stride = gridDim.x * blockDim.x;
    if (i < NY) g_flag[i] = 0;
    for (int idx = i; idx < 1024 * EMB; idx += stride)
        g_wsum[idx] = Wih[idx] + Whh[idx];
    for (int idx = i; idx < 1024; idx += stride)
        g_bsum[idx] = bih[idx] + bhh[idx];
    for (int idx = i; idx < 361 * EMB; idx += stride) {
        int j = idx >> 8;
        int e = idx & 255;
        g_WlinT[idx] = Wlin[e * 361 + j];
    }
}

// ---------------- K1 ----------------
__device__ __forceinline__ float block_sum512(float v, float* red16) {
#pragma unroll
    for (int o = 16; o; o >>= 1) v += __shfl_xor_sync(0xffffffffu, v, o);
    __syncthreads();
    if ((threadIdx.x & 31) == 0) red16[threadIdx.x >> 5] = v;
    __syncthreads();
    float s = 0.f;
#pragma unroll
    for (int i = 0; i < 16; i++) s += red16[i];
    return s;
}

__global__ void k1_prep(const float* __restrict__ board,
                        const float* __restrict__ conv_w,
                        const float* __restrict__ conv_b,
                        const float* __restrict__ bn_gamma,
                        const float* __restrict__ bn_beta,
                        const float* __restrict__ p,
                        const float* __restrict__ b_lin) {
    __shared__ float A[441];
    __shared__ float B[441];
    __shared__ float d2s[361];
    __shared__ float red16[16];

    int tid = threadIdx.x;
    float w[9];
#pragma unroll
    for (int q = 0; q < 9; q++) w[q] = conv_w[q];
    float cbias = conv_b[0], gamma = bn_gamma[0], beta = bn_beta[0];

    if (tid < 441) { A[tid] = 0.f; B[tid] = 0.f; }
    __syncthreads();
    if (tid < 361) {
        int r = tid / 19, c = tid % 19;
        A[(r + 1) * 21 + (c + 1)] = board[tid];
    }
    __syncthreads();

    float* src = A;
    float* dst = B;
    const int types[8] = {0, 0, 1, 0, 1, 0, 1, 2};
    const int pidx[8]  = {0, 1, 2, 3, 4, 5, 6, 0};

    for (int st = 0; st < 8; st++) {
        float y = 0.f;
        int base = 0;
        if (tid < 361) {
            int r = tid / 19, c = tid % 19;
            base = (r + 1) * 21 + (c + 1);
#pragma unroll
            for (int ki = 0; ki < 3; ki++)
#pragma unroll
                for (int kj = 0; kj < 3; kj++)
                    y += w[ki * 3 + kj] * src[base + (ki - 1) * 21 + (kj - 1)];
            y += cbias;
        }
        float mu = block_sum512((tid < 361) ? y : 0.f, red16) * (1.f / 361.f);
        float d = (tid < 361) ? (y - mu) : 0.f;
        float var = block_sum512(d * d, red16) * (1.f / 361.f);
        float rstd = rsqrtf(var + BN_EPS);

        if (tid < 361) {
            float z = gamma * (y - mu) * rstd + beta;
            float v;
            int t = types[st];
            if (t == 0)      v = fmaxf(p[pidx[st]] * z, 0.f);
            else if (t == 1) v = fmaxf(p[pidx[st]] * z + d2s[tid], 0.f);
            else             v = fmaxf(z, 0.f);
            dst[base] = v;
            if (st == 0 || t == 1) d2s[tid] = v;
        }
        __syncthreads();
        float* tmp = src; src = dst; dst = tmp;
    }

    if (tid < 361) {
        int r = tid / 19, c = tid % 19;
        d2s[tid] = src[(r + 1) * 21 + (c + 1)];
    }
    __syncthreads();

    if (tid < 256) {
        float acc = b_lin[tid];
        for (int j = 0; j < 361; j++)
            acc += g_WlinT[j * 256 + tid] * d2s[j];
        g_feat[tid] = acc;
    }
}

// ---------------- cluster / mbarrier helpers ----------------
__device__ __forceinline__ void cluster_sync_() {
    asm volatile("barrier.cluster.arrive.aligned;" ::: "memory");
    asm volatile("barrier.cluster.wait.aligned;" ::: "memory");
}
__device__ __forceinline__ unsigned smem_u32(const void* p) {
    unsigned a;
    asm("{ .reg .u64 t; cvta.to.shared.u64 t, %1; cvt.u32.u64 %0, t; }"
        : "=r"(a) : "l"(p));
    return a;
}
__device__ __forceinline__ void mbar_init_(unsigned addr, unsigned cnt) {
    asm volatile("mbarrier.init.shared.b64 [%0], %1;" :: "r"(addr), "r"(cnt) : "memory");
}
__device__ __forceinline__ void mbar_arrive_expect(unsigned addr, unsigned tx) {
    asm volatile("mbarrier.arrive.expect_tx.shared.b64 _, [%0], %1;"
                 :: "r"(addr), "r"(tx) : "memory");
}
__device__ __forceinline__ void mbar_wait_cluster(unsigned addr, unsigned parity) {
    unsigned done;
    asm volatile(
        "{\n\t.reg .pred p;\n\t"
        "mbarrier.try_wait.parity.acquire.cluster.shared::cta.b64 p, [%1], %2, 0x989680;\n\t"
        "selp.b32 %0, 1, 0, p;\n\t}"
        : "=r"(done) : "r"(addr), "r"(parity) : "memory");
    while (!done) {
        asm volatile(
            "{\n\t.reg .pred p;\n\t"
            "mbarrier.try_wait.parity.acquire.cluster.shared::cta.b64 p, [%1], %2, 0x989680;\n\t"
            "selp.b32 %0, 1, 0, p;\n\t}"
            : "=r"(done) : "r"(addr), "r"(parity) : "memory");
    }
}
__device__ __forceinline__ void st_async_remote(unsigned daddr, unsigned dmbar,
                                                int rk, float v) {
    unsigned ra, rm;
    asm volatile("mapa.shared::cluster.u32 %0, %1, %2;" : "=r"(ra) : "r"(daddr), "r"(rk));
    asm volatile("mapa.shared::cluster.u32 %0, %1, %2;" : "=r"(rm) : "r"(dmbar), "r"(rk));
    asm volatile("st.async.shared::cluster.mbarrier::complete_tx::bytes.f32 [%0], %1, [%2];"
                 :: "r"(ra), "f"(v), "r"(rm) : "memory");
}
__device__ __forceinline__ float fsig(float x) {
    return __fdividef(1.f, 1.f + __expf(-x));
}
__device__ __forceinline__ float ftanh_(float x) {
    float e = __expf(2.f * x);
    return 1.f - __fdividef(2.f, e + 1.f);
}

__device__ __forceinline__ void publish_flag(int y, int tid) {
    __syncthreads();
    if (tid == 0) {
        __threadfence();
        atomicAdd(&g_flag[y], 1);
    }
}

// ================= fused kernel =================
// CTAs 0..7: LSTM cluster. CTAs 8..: decode tiles (256 vocab x 13 rows).
__global__ void __cluster_dims__(8, 1, 1) __launch_bounds__(512, 1)
k2_fused(const float* __restrict__ Wih,
         const float* __restrict__ W_dec,
         const float* __restrict__ b_dec,
         float* __restrict__ out) {
    extern __shared__ __align__(16) float dsm[];
    int tid = threadIdx.x;
    int bid = blockIdx.x;

    if (bid < NLSTM) {
        // ---------------- LSTM part ----------------
        __shared__ __align__(16) float h_buf[2][256];
        __shared__ unsigned long long mbar_s[2];

        int rank = bid;
        int jbase = rank * 32;
        int g = tid >> 4;      // 0..31
        int sk = tid & 15;     // k slice of 16 floats

        unsigned mb0 = smem_u32(&mbar_s[0]);
        unsigned mb1 = smem_u32(&mbar_s[1]);

        if (tid == 0) {
            mbar_init_(mb0, 1);
            mbar_init_(mb1, 1);
            mbar_arrive_expect(mb1, 1024);
            mbar_arrive_expect(mb0, 1024);
        }
        if (tid < 256) h_buf[0][tid] = g_feat[tid];

        float bi[4];
#pragma unroll
        for (int sec = 0; sec < 4; sec++) bi[sec] = g_bsum[sec * 256 + jbase + g];

        ulonglong2 wr[4][4];
#pragma unroll
        for (int sec = 0; sec < 4; sec++) {
            const ulonglong2* wp = (const ulonglong2*)
                (g_wsum + (sec * 256 + jbase + g) * 256 + sk * 16);
#pragma unroll
            for (int q = 0; q < 4; q++) wr[sec][q] = wp[q];
        }
        __syncthreads();
        cluster_sync_();

        float c = 0.f;
        int par0 = 0, par1 = 0;

        // step 0: gates = W_ih @ feat
        {
            const ulonglong2* hb = (const ulonglong2*)(&h_buf[0][sk * 16]);
            ulonglong2 hq[4] = { hb[0], hb[1], hb[2], hb[3] };
            float fs[4];
#pragma unroll
            for (int sec = 0; sec < 4; sec++) {
                const ulonglong2* wp = (const ulonglong2*)
                    (Wih + (sec * 256 + jbase + g) * 256 + sk * 16);
                unsigned long long a0 = 0ull, a1 = 0ull;
#pragma unroll
                for (int q = 0; q < 4; q++) {
                    ulonglong2 wv = wp[q];
                    FMA2(a0, wv.x, hq[q].x);
                    FMA2(a1, wv.y, hq[q].y);
                }
                float l0, h0, l1, h1;
                UNPACK64(l0, h0, a0); UNPACK64(l1, h1, a1);
                fs[sec] = (l0 + h0) + (l1 + h1);
            }
#pragma unroll
            for (int m = 1; m < 16; m <<= 1)
#pragma unroll
                for (int sec = 0; sec < 4; sec++)
                    fs[sec] += __shfl_xor_sync(0xffffffffu, fs[sec], m);
            if (sk == 0) {
                float gi = fsig(fs[0] + bi[0]);
                float gf = fsig(fs[1] + bi[1]);
                float gg = ftanh_(fs[2] + bi[2]);
                float go = fsig(fs[3] + bi[3]);
                c = gf * c + gi * gg;
                float h = go * ftanh_(c);
                g_H[jbase + g] = h;
                unsigned da = smem_u32(&h_buf[1][jbase + g]);
#pragma unroll
                for (int rk = 0; rk < 8; rk++) st_async_remote(da, mb1, rk, h);
            }
        }

        // steps 1..100
        for (int s = 1; s <= 100; s++) {
            int b = s & 1;
            unsigned mb = b ? mb1 : mb0;
            mbar_wait_cluster(mb, b ? par1 : par0);
            if (b) par1 ^= 1; else par0 ^= 1;
            if (tid == 0 && s <= 98) mbar_arrive_expect(mb, 1024);

            const ulonglong2* hb = (const ulonglong2*)(&h_buf[b][sk * 16]);
            ulonglong2 hq[4] = { hb[0], hb[1], hb[2], hb[3] };
            float fs[4];
#pragma unroll
            for (int sec = 0; sec < 4; sec++) {
                unsigned long long a0 = 0ull, a1 = 0ull;
#pragma unroll
                for (int q = 0; q < 4; q++) {
                    FMA2(a0, wr[sec][q].x, hq[q].x);
                    FMA2(a1, wr[sec][q].y, hq[q].y);
                }
                float l0, h0, l1, h1;
                UNPACK64(l0, h0, a0); UNPACK64(l1, h1, a1);
                fs[sec] = (l0 + h0) + (l1 + h1);
            }
#pragma unroll
            for (int m = 1; m < 16; m <<= 1)
#pragma unroll
                for (int sec = 0; sec < 4; sec++)
                    fs[sec] += __shfl_xor_sync(0xffffffffu, fs[sec], m);

            if (sk == 0) {
                float gi = fsig(fs[0] + bi[0]);
                float gf = fsig(fs[1] + bi[1]);
                float gg = ftanh_(fs[2] + bi[2]);
                float go = fsig(fs[3] + bi[3]);
                c = gf * c + gi * gg;
                float h = go * ftanh_(c);
                g_H[s * 256 + jbase + g] = h;
                if (s < 100) {
                    int nb = (s + 1) & 1;
                    unsigned da = smem_u32(&h_buf[nb][jbase + g]);
                    unsigned dm = nb ? mb1 : mb0;
#pragma unroll
                    for (int rk = 0; rk < 8; rk++) st_async_remote(da, dm, rk, h);
                }
            }
            // publish finished row blocks
            if (s == 100) publish_flag(7, tid);
            else if (s >= 12 && s <= 90 && ((s - 12) % 13) == 0)
                publish_flag((s - 12) / 13, tid);
        }
        return;
    }

    // ---------------- decode part ----------------
    float* Wb[2] = { dsm, dsm + 8192 };   // 32k x 256v each
    float* Hs = dsm + 16384;              // 256k x 16 row slots

    int dcta = bid - NLSTM;
    int xt = dcta % NXT, yb = dcta / NXT;
    int vbase = xt * 256;
    int rbase = yb * 13;
    int vg = tid & 63;       // vocab quad
    int kp = tid >> 6;       // k-phase 0..7 (4 k per chunk)

    // wait for our row block
    if (tid == 0) {
        volatile int* fp = g_flag + yb;
        while (*fp < NLSTM) __nanosleep(256);
        __threadfence();
    }
    __syncthreads();

    // stage all H rows for this block, transposed [k][slot16]
    for (int idx = tid; idx < 4096; idx += 512) {
        int slot = idx >> 8;     // 0..15
        int k = idx & 255;
        float v = 0.f;
        int row = rbase + slot;
        if (slot < 13 && row < ROWS_OUT) v = __ldcg(g_H + row * 256 + k);
        Hs[k * 16 + slot] = v;
    }

    unsigned long long acc[6][4];
#pragma unroll
    for (int p2 = 0; p2 < 6; p2++)
#pragma unroll
        for (int c2 = 0; c2 < 4; c2++) acc[p2][c2] = 0ull;
    float acc12[4] = {0.f, 0.f, 0.f, 0.f};

    float4 w4[4];
    // prefetch chunk 0 (W tile 32k x 256v)
#pragma unroll
    for (int i = 0; i < 4; i++) {
        int F = tid + 512 * i;
        int vcol = F >> 3, kq = F & 7;
        int v = vbase + vcol; if (v >= VOCAB) v = VOCAB - 1;
        w4[i] = *(const float4*)(W_dec + v * 256 + kq * 4);
    }

    for (int cch = 0; cch < 8; cch++) {
        float* W = Wb[cch & 1];
#pragma unroll
        for (int i = 0; i < 4; i++) {
            int F = tid + 512 * i;
            int vcol = F >> 3, kq = F & 7;
            int cs = vcol ^ (kq << 2);
            W[(kq * 4 + 0) * 256 + cs] = w4[i].x;
            W[(kq * 4 + 1) * 256 + cs] = w4[i].y;
            W[(kq * 4 + 2) * 256 + cs] = w4[i].z;
            W[(kq * 4 + 3) * 256 + cs] = w4[i].w;
        }
        __syncthreads();
        if (cch < 7) {
#pragma unroll
            for (int i = 0; i < 4; i++) {
                int F = tid + 512 * i;
                int vcol = F >> 3, kq = F & 7;
                int v = vbase + vcol; if (v >= VOCAB) v = VOCAB - 1;
                w4[i] = *(const float4*)(W_dec + v * 256 + (cch + 1) * 32 + kq * 4);
            }
        }
#pragma unroll
        for (int j = 0; j < 4; j++) {
            int kk = kp * 4 + j;                 // within chunk
            float4 wq = *(const float4*)(W + kk * 256 + 4 * (vg ^ (kk >> 2)));
            const float* hrow = Hs + (cch * 32 + kk) * 16;
            ulonglong2 hA = *(const ulonglong2*)(hrow);
            ulonglong2 hB = *(const ulonglong2*)(hrow + 4);
            ulonglong2 hC = *(const ulonglong2*)(hrow + 8);
            float h12 = hrow[12];
            unsigned long long wd0, wd1, wd2, wd3;
            DUP2(wd0, wq.x); DUP2(wd1, wq.y); DUP2(wd2, wq.z); DUP2(wd3, wq.w);
            FMA2(acc[0][0], hA.x, wd0); FMA2(acc[0][1], hA.x, wd1);
            FMA2(acc[0][2], hA.x, wd2); FMA2(acc[0][3], hA.x, wd3);
            FMA2(acc[1][0], hA.y, wd0); FMA2(acc[1][1], hA.y, wd1);
            FMA2(acc[1][2], hA.y, wd2); FMA2(acc[1][3], hA.y, wd3);
            FMA2(acc[2][0], hB.x, wd0); FMA2(acc[2][1], hB.x, wd1);
            FMA2(acc[2][2], hB.x, wd2); FMA2(acc[2][3], hB.x, wd3);
            FMA2(acc[3][0], hB.y, wd0); FMA2(acc[3][1], hB.y, wd1);
            FMA2(acc[3][2], hB.y, wd2); FMA2(acc[3][3], hB.y, wd3);
            FMA2(acc[4][0], hC.x, wd0); FMA2(acc[4][1], hC.x, wd1);
            FMA2(acc[4][2], hC.x, wd2); FMA2(acc[4][3], hC.x, wd3);
            FMA2(acc[5][0], hC.y, wd0); FMA2(acc[5][1], hC.y, wd1);
            FMA2(acc[5][2], hC.y, wd2); FMA2(acc[5][3], hC.y, wd3);
            acc12[0] = fmaf(h12, wq.x, acc12[0]);
            acc12[1] = fmaf(h12, wq.y, acc12[1]);
            acc12[2] = fmaf(h12, wq.z, acc12[2]);
            acc12[3] = fmaf(h12, wq.w, acc12[3]);
        }
        __syncthreads();
    }

    // reduce 8 k-phases -> phase 0 (tree through smem)
    unsigned long long* Rb = (unsigned long long*)dsm;
#pragma unroll
    for (int half = 4; half >= 1; half >>= 1) {
        if (kp >= half && kp < 2 * half) {
            int base = (tid - half * 64) * 27;
#pragma unroll
            for (int p2 = 0; p2 < 6; p2++)
#pragma unroll
                for (int c2 = 0; c2 < 4; c2++)
                    Rb[base + p2 * 4 + c2] = acc[p2][c2];
            unsigned long long pk0, pk1;
            PACK64(pk0, acc12[0], acc12[1]);
            PACK64(pk1, acc12[2], acc12[3]);
            Rb[base + 24] = pk0;
            Rb[base + 25] = pk1;
        }
        __syncthreads();
        if (kp < half) {
            int base = tid * 27;
#pragma unroll
            for (int p2 = 0; p2 < 6; p2++)
#pragma unroll
                for (int c2 = 0; c2 < 4; c2++)
                    ADD2(acc[p2][c2], Rb[base + p2 * 4 + c2]);
            float a0, a1;
            UNPACK64(a0, a1, Rb[base + 24]);
            acc12[0] += a0; acc12[1] += a1;
            UNPACK64(a0, a1, Rb[base + 25]);
            acc12[2] += a0; acc12[3] += a1;
        }
        __syncthreads();
    }

    if (kp == 0) {
        int v0 = vbase + vg * 4;
        if (v0 < VOCAB) {
            float4 bv = *(const float4*)(b_dec + v0);
            float bb[4] = {bv.x, bv.y, bv.z, bv.w};
            float rows[13][4];
#pragma unroll
            for (int c2 = 0; c2 < 4; c2++) {
                float lo, hi;
                UNPACK64(lo, hi, acc[0][c2]); rows[0][c2] = lo; rows[1][c2] = hi;
                UNPACK64(lo, hi, acc[1][c2]); rows[2][c2] = lo; rows[3][c2] = hi;
                UNPACK64(lo, hi, acc[2][c2]); rows[4][c2] = lo; rows[5][c2] = hi;
                UNPACK64(lo, hi, acc[3][c2]); rows[6][c2] = lo; rows[7][c2] = hi;
                UNPACK64(lo, hi, acc[4][c2]); rows[8][c2] = lo; rows[9][c2] = hi;
                UNPACK64(lo, hi, acc[5][c2]); rows[10][c2] = lo; rows[11][c2] = hi;
                rows[12][c2] = acc12[c2];
            }
#pragma unroll
            for (int rr = 0; rr < 13; rr++) {
                int row = rbase + rr;
                if (row < ROWS_OUT) {
                    float4 o;
                    o.x = fmaxf(rows[rr][0] + bb[0], 0.f);
                    o.y = fmaxf(rows[rr][1] + bb[1], 0.f);
                    o.z = fmaxf(rows[rr][2] + bb[2], 0.f);
                    o.w = fmaxf(rows[rr][3] + bb[3], 0.f);
                    *(float4*)(out + row * VOCAB + v0) = o;
                }
            }
        }
    }
}

// ---------------- launch ----------------
extern "C" void kernel_launch(void* const* d_in, const int* in_sizes, int n_in,
                              void* d_out, int out_size) {
    const float* board    = (const float*)d_in[0];
    const float* conv_w   = (const float*)d_in[1];
    const float* conv_b   = (const float*)d_in[2];
    const float* bn_gamma = (const float*)d_in[3];
    const float* bn_beta  = (const float*)d_in[4];
    const float* p        = (const float*)d_in[5];
    const float* W_lin    = (const float*)d_in[6];
    const float* b_lin    = (const float*)d_in[7];
    const float* W_ih     = (const float*)d_in[8];
    const float* b_ih     = (const float*)d_in[9];
    const float* W_hh     = (const float*)d_in[10];
    const float* b_hh     = (const float*)d_in[11];
    const float* W_dec    = (const float*)d_in[12];
    const float* b_dec    = (const float*)d_in[13];
    float* out = (float*)d_out;

    // dynamic smem: W 2x8192 + Hs 4096 floats = 20480 floats = 81920 B
    size_t smf = 20480 * sizeof(float);
    cudaFuncSetAttribute(k2_fused, cudaFuncAttributeMaxDynamicSharedMemorySize, (int)smf);

    k0_precompute<<<256, 256>>>(W_ih, W_hh, b_ih, b_hh, W_lin);
    k1_prep<<<1, 512>>>(board, conv_w, conv_b, bn_gamma, bn_beta, p, b_lin);
    k2_fused<<<GRID_FUSED, 512, smf>>>(W_ih, W_dec, b_dec, out);
}

// round 6
// speedup vs baseline: 1.3555x; 1.3555x over previous
#include <cuda_runtime.h>
#include <math.h>

#define EMB 256
#define VOCAB 50000
#define ROWS_OUT 101
#define BN_EPS 1e-5f
#define NLSTM 8
#define NY 4
#define HT_STRIDE 104

// ---------------- packed f32x2 helpers ----------------
#define FMA2(acc, a, b) \
    asm("fma.rn.f32x2 %0, %1, %2, %0;" : "+l"(acc) : "l"(a), "l"(b))
#define ADD2(acc, b) \
    asm("add.rn.f32x2 %0, %0, %1;" : "+l"(acc) : "l"(b))
#define UNPACK64(lo, hi, v) do { unsigned _ulo, _uhi; \
    asm("mov.b64 {%0, %1}, %2;" : "=r"(_ulo), "=r"(_uhi) : "l"(v)); \
    lo = __uint_as_float(_ulo); hi = __uint_as_float(_uhi); } while (0)
#define DUP2(d, f) do { unsigned _u = __float_as_uint(f); \
    asm("mov.b64 %0, {%1, %1};" : "=l"(d) : "r"(_u)); } while (0)

// ---------------- device scratch ----------------
__device__ float g_WlinT[361 * EMB];
__device__ float g_feat[EMB];
__device__ float g_Ht[EMB * HT_STRIDE];   // transposed H: [k][step]
__device__ int g_flag[NY];

// ---------------- K0: W_lin transpose + flag reset ----------------
__global__ void k0_precompute(const float* __restrict__ Wlin) {
    int i = blockIdx.x * blockDim.x + threadIdx.x;
    int stride = gridDim.x * blockDim.x;
    if (i < NY) g_flag[i] = 0;
    for (int idx = i; idx < 361 * EMB; idx += stride) {
        int j = idx >> 8;
        int e = idx & 255;
        g_WlinT[idx] = Wlin[e * 361 + j];
    }
}

// ---------------- K1: conv/BN stack + feat ----------------
__device__ __forceinline__ float block_sum512(float v, float* red16) {
#pragma unroll
    for (int o = 16; o; o >>= 1) v += __shfl_xor_sync(0xffffffffu, v, o);
    __syncthreads();
    if ((threadIdx.x & 31) == 0) red16[threadIdx.x >> 5] = v;
    __syncthreads();
    float s = 0.f;
#pragma unroll
    for (int i = 0; i < 16; i++) s += red16[i];
    return s;
}

__global__ void k1_prep(const float* __restrict__ board,
                        const float* __restrict__ conv_w,
                        const float* __restrict__ conv_b,
                        const float* __restrict__ bn_gamma,
                        const float* __restrict__ bn_beta,
                        const float* __restrict__ p,
                        const float* __restrict__ b_lin) {
    __shared__ float A[441];
    __shared__ float B[441];
    __shared__ float d2s[361];
    __shared__ float red16[16];

    int tid = threadIdx.x;
    float w[9];
#pragma unroll
    for (int q = 0; q < 9; q++) w[q] = conv_w[q];
    float cbias = conv_b[0], gamma = bn_gamma[0], beta = bn_beta[0];

    if (tid < 441) { A[tid] = 0.f; B[tid] = 0.f; }
    __syncthreads();
    if (tid < 361) {
        int r = tid / 19, c = tid % 19;
        A[(r + 1) * 21 + (c + 1)] = board[tid];
    }
    __syncthreads();

    float* src = A;
    float* dst = B;
    const int types[8] = {0, 0, 1, 0, 1, 0, 1, 2};
    const int pidx[8]  = {0, 1, 2, 3, 4, 5, 6, 0};

    for (int st = 0; st < 8; st++) {
        float y = 0.f;
        int base = 0;
        if (tid < 361) {
            int r = tid / 19, c = tid % 19;
            base = (r + 1) * 21 + (c + 1);
#pragma unroll
            for (int ki = 0; ki < 3; ki++)
#pragma unroll
                for (int kj = 0; kj < 3; kj++)
                    y += w[ki * 3 + kj] * src[base + (ki - 1) * 21 + (kj - 1)];
            y += cbias;
        }
        float mu = block_sum512((tid < 361) ? y : 0.f, red16) * (1.f / 361.f);
        float d = (tid < 361) ? (y - mu) : 0.f;
        float var = block_sum512(d * d, red16) * (1.f / 361.f);
        float rstd = rsqrtf(var + BN_EPS);

        if (tid < 361) {
            float z = gamma * (y - mu) * rstd + beta;
            float v;
            int t = types[st];
            if (t == 0)      v = fmaxf(p[pidx[st]] * z, 0.f);
            else if (t == 1) v = fmaxf(p[pidx[st]] * z + d2s[tid], 0.f);
            else             v = fmaxf(z, 0.f);
            dst[base] = v;
            if (st == 0 || t == 1) d2s[tid] = v;
        }
        __syncthreads();
        float* tmp = src; src = dst; dst = tmp;
    }

    if (tid < 361) {
        int r = tid / 19, c = tid % 19;
        d2s[tid] = src[(r + 1) * 21 + (c + 1)];
    }
    __syncthreads();

    if (tid < 256) {
        float acc = b_lin[tid];
        for (int j = 0; j < 361; j++)
            acc += g_WlinT[j * 256 + tid] * d2s[j];
        g_feat[tid] = acc;
    }
}

// ---------------- cluster / mbarrier helpers ----------------
__device__ __forceinline__ void cluster_sync_() {
    asm volatile("barrier.cluster.arrive.aligned;" ::: "memory");
    asm volatile("barrier.cluster.wait.aligned;" ::: "memory");
}
__device__ __forceinline__ unsigned smem_u32(const void* p) {
    unsigned a;
    asm("{ .reg .u64 t; cvta.to.shared.u64 t, %1; cvt.u32.u64 %0, t; }"
        : "=r"(a) : "l"(p));
    return a;
}
__device__ __forceinline__ void mbar_init_(unsigned addr, unsigned cnt) {
    asm volatile("mbarrier.init.shared.b64 [%0], %1;" :: "r"(addr), "r"(cnt) : "memory");
}
__device__ __forceinline__ void mbar_arrive_expect(unsigned addr, unsigned tx) {
    asm volatile("mbarrier.arrive.expect_tx.shared.b64 _, [%0], %1;"
                 :: "r"(addr), "r"(tx) : "memory");
}
__device__ __forceinline__ void mbar_wait_cluster(unsigned addr, unsigned parity) {
    unsigned done;
    asm volatile(
        "{\n\t.reg .pred p;\n\t"
        "mbarrier.try_wait.parity.acquire.cluster.shared::cta.b64 p, [%1], %2, 0x989680;\n\t"
        "selp.b32 %0, 1, 0, p;\n\t}"
        : "=r"(done) : "r"(addr), "r"(parity) : "memory");
    while (!done) {
        asm volatile(
            "{\n\t.reg .pred p;\n\t"
            "mbarrier.try_wait.parity.acquire.cluster.shared::cta.b64 p, [%1], %2, 0x989680;\n\t"
            "selp.b32 %0, 1, 0, p;\n\t}"
            : "=r"(done) : "r"(addr), "r"(parity) : "memory");
    }
}
__device__ __forceinline__ void st_async_remote(unsigned daddr, unsigned dmbar,
                                                int rk, float v) {
    unsigned ra, rm;
    asm volatile("mapa.shared::cluster.u32 %0, %1, %2;" : "=r"(ra) : "r"(daddr), "r"(rk));
    asm volatile("mapa.shared::cluster.u32 %0, %1, %2;" : "=r"(rm) : "r"(dmbar), "r"(rk));
    asm volatile("st.async.shared::cluster.mbarrier::complete_tx::bytes.f32 [%0], %1, [%2];"
                 :: "r"(ra), "f"(v), "r"(rm) : "memory");
}
__device__ __forceinline__ float fsig(float x) {
    return __fdividef(1.f, 1.f + __expf(-x));
}
__device__ __forceinline__ float ftanh_(float x) {
    float e = __expf(2.f * x);
    return 1.f - __fdividef(2.f, e + 1.f);
}

// ---------------- K2: cluster-of-8 LSTM (PDL primary) ----------------
// Launched with 180KB dummy dynamic smem so no decode CTA can co-reside.
__global__ void __cluster_dims__(8, 1, 1) __launch_bounds__(256, 1)
k2_lstm(const float* __restrict__ Wih, const float* __restrict__ Whh,
        const float* __restrict__ bih, const float* __restrict__ bhh) {
    // let the decode grid launch right away
    asm volatile("griddepcontrol.launch_dependents;");

    __shared__ __align__(16) float h_buf[2][256];
    __shared__ unsigned long long mbar_s[2];

    int tid = threadIdx.x;
    int rank = blockIdx.x;
    int jbase = rank * 32;
    int sk = tid & 7;
    int g = tid >> 3;

    unsigned mb0 = smem_u32(&mbar_s[0]);
    unsigned mb1 = smem_u32(&mbar_s[1]);

    if (tid == 0) {
        mbar_init_(mb0, 1);
        mbar_init_(mb1, 1);
        mbar_arrive_expect(mb1, 1024);
        mbar_arrive_expect(mb0, 1024);
    }
    h_buf[0][tid] = g_feat[tid];

    float bi[4];
#pragma unroll
    for (int sec = 0; sec < 4; sec++)
        bi[sec] = bih[sec * 256 + jbase + g] + bhh[sec * 256 + jbase + g];

    // weights: wsum computed in-register (rotated chunk order)
    ulonglong2 wr[4][8];
#pragma unroll
    for (int sec = 0; sec < 4; sec++) {
        const float* baseI = Wih + (sec * 256 + jbase + g) * 256 + sk * 32;
        const float* baseH = Whh + (sec * 256 + jbase + g) * 256 + sk * 32;
#pragma unroll
        for (int q = 0; q < 8; q++) {
            int qq = q ^ sk;
            ulonglong2 a = *(const ulonglong2*)(baseI + qq * 4);
            ulonglong2 b = *(const ulonglong2*)(baseH + qq * 4);
            ADD2(a.x, b.x);
            ADD2(a.y, b.y);
            wr[sec][q] = a;
        }
    }
    __syncthreads();
    cluster_sync_();

    float c = 0.f;
    int par0 = 0, par1 = 0;

    // ---- step 0: gates = W_ih @ feat ----
    {
        unsigned long long a[4][2];
#pragma unroll
        for (int sec = 0; sec < 4; sec++) { a[sec][0] = 0ull; a[sec][1] = 0ull; }
        const ulonglong2* hb = (const ulonglong2*)(&h_buf[0][sk * 32]);
#pragma unroll
        for (int q = 0; q < 8; q++) {
            int qq = q ^ sk;
            ulonglong2 hx = hb[qq];
#pragma unroll
            for (int sec = 0; sec < 4; sec++) {
                ulonglong2 wv = *(const ulonglong2*)
                    (Wih + (sec * 256 + jbase + g) * 256 + sk * 32 + qq * 4);
                FMA2(a[sec][0], wv.x, hx.x);
                FMA2(a[sec][1], wv.y, hx.y);
            }
        }
        float fs[4];
#pragma unroll
        for (int sec = 0; sec < 4; sec++) {
            float l0, h0, l1, h1;
            UNPACK64(l0, h0, a[sec][0]);
            UNPACK64(l1, h1, a[sec][1]);
            fs[sec] = (l0 + h0) + (l1 + h1);
        }
#pragma unroll
        for (int m = 1; m < 8; m <<= 1)
#pragma unroll
            for (int sec = 0; sec < 4; sec++)
                fs[sec] += __shfl_xor_sync(0xffffffffu, fs[sec], m);
        if (sk == 0) {
            float gi = fsig(fs[0] + bi[0]);
            float gf = fsig(fs[1] + bi[1]);
            float gg = ftanh_(fs[2] + bi[2]);
            float go = fsig(fs[3] + bi[3]);
            c = gf * c + gi * gg;
            float h = go * ftanh_(c);
            g_Ht[(jbase + g) * HT_STRIDE + 0] = h;
            unsigned da = smem_u32(&h_buf[1][jbase + g]);
#pragma unroll
            for (int rk = 0; rk < 8; rk++) st_async_remote(da, mb1, rk, h);
        }
    }

    // ---- steps 1..100 ----
    for (int s = 1; s <= 100; s++) {
        int b = s & 1;
        unsigned mb = b ? mb1 : mb0;
        mbar_wait_cluster(mb, b ? par1 : par0);
        if (b) par1 ^= 1; else par0 ^= 1;
        if (tid == 0 && s <= 98) mbar_arrive_expect(mb, 1024);

        unsigned long long a[4][2];
#pragma unroll
        for (int sec = 0; sec < 4; sec++) { a[sec][0] = 0ull; a[sec][1] = 0ull; }
        const ulonglong2* hb = (const ulonglong2*)(&h_buf[b][sk * 32]);
#pragma unroll
        for (int q = 0; q < 8; q++) {
            ulonglong2 hx = hb[q ^ sk];
#pragma unroll
            for (int sec = 0; sec < 4; sec++) {
                FMA2(a[sec][0], wr[sec][q].x, hx.x);
                FMA2(a[sec][1], wr[sec][q].y, hx.y);
            }
        }
        float fs[4];
#pragma unroll
        for (int sec = 0; sec < 4; sec++) {
            float l0, h0, l1, h1;
            UNPACK64(l0, h0, a[sec][0]);
            UNPACK64(l1, h1, a[sec][1]);
            fs[sec] = (l0 + h0) + (l1 + h1);
        }
#pragma unroll
        for (int m = 1; m < 8; m <<= 1)
#pragma unroll
            for (int sec = 0; sec < 4; sec++)
                fs[sec] += __shfl_xor_sync(0xffffffffu, fs[sec], m);

        if (sk == 0) {
            float gi = fsig(fs[0] + bi[0]);
            float gf = fsig(fs[1] + bi[1]);
            float gg = ftanh_(fs[2] + bi[2]);
            float go = fsig(fs[3] + bi[3]);
            c = gf * c + gi * gg;
            float h = go * ftanh_(c);
            g_Ht[(jbase + g) * HT_STRIDE + s] = h;
            if (s < 100) {
                int nb = (s + 1) & 1;
                unsigned da = smem_u32(&h_buf[nb][jbase + g]);
                unsigned dm = nb ? mb1 : mb0;
#pragma unroll
                for (int rk = 0; rk < 8; rk++) st_async_remote(da, dm, rk, h);
            }
        }
        // publish row-block readiness (rows [y*26, y*26+25] ready at s = y*26+25)
        if (s == 25 || s == 51 || s == 77) {
            __syncthreads();
            if (tid == 0) {
                __threadfence();
                atomicAdd(&g_flag[s / 26], 1);
            }
        }
    }
    __syncthreads();
    if (tid == 0) {
        __threadfence();
        atomicAdd(&g_flag[3], 1);
    }
}

// ---------------- K3: decode (PDL secondary) ----------------
// grid (391, 4): 128-vocab x 26-row tiles. Thread: 4 rows x 4 vocab.
// H staged as duplicated f32x2 pairs -> inner loop = 3 LDS.128 + 8 FMA2 per kk.
__global__ void __launch_bounds__(256, 3)
k3_decode(const float* __restrict__ W_dec,
          const float* __restrict__ b_dec,
          float* __restrict__ out) {
    extern __shared__ __align__(16) float dsm[];
    // [0,4096) W buf0, [4096,8192) W buf1, then 2 x 1024 ull H buffers

    int tid = threadIdx.x;
    int vbase = blockIdx.x * 128;
    int yb = blockIdx.y;
    int rbase = yb * 26;
    int nrows = (yb == 3) ? (ROWS_OUT - 78) : 26;
    int vg = tid & 31, rg = tid >> 5;
    int v0 = vbase + vg * 4;
    int slot = tid & 31;
    int cslot = slot < nrows ? slot : nrows - 1;

    // wait until all 8 LSTM CTAs have written our row block
    if (tid == 0) {
        while (atomicAdd(&g_flag[yb], 0) < NLSTM) __nanosleep(128);
    }
    __syncthreads();
    __threadfence();

    unsigned long long acc[4][2];
#pragma unroll
    for (int r = 0; r < 4; r++) { acc[r][0] = 0ull; acc[r][1] = 0ull; }

    float4 w4[4];
    float hv[4];
    // prefetch chunk 0
#pragma unroll
    for (int q = 0; q < 4; q++) {
        int F = tid + 256 * q;
        int kq = F & 7, vcol = F >> 3;
        int v = vbase + vcol; if (v >= VOCAB) v = VOCAB - 1;
        w4[q] = *(const float4*)(W_dec + v * 256 + kq * 4);
    }
#pragma unroll
    for (int t = 0; t < 4; t++) {
        int k = rg + 8 * t;
        hv[t] = __ldcg(g_Ht + k * HT_STRIDE + rbase + cslot);
    }

    for (int kc = 0; kc < 8; kc++) {
        float* W = dsm + (kc & 1) * 4096;
        unsigned long long* H = (unsigned long long*)(dsm + 8192) + (kc & 1) * 1024;
        // stage W (swizzled) and H (duplicated pairs)
#pragma unroll
        for (int q = 0; q < 4; q++) {
            int F = tid + 256 * q;
            int kq = F & 7, vcol = F >> 3;
            int cs = vcol ^ (kq << 2);
            W[(kq * 4 + 0) * 128 + cs] = w4[q].x;
            W[(kq * 4 + 1) * 128 + cs] = w4[q].y;
            W[(kq * 4 + 2) * 128 + cs] = w4[q].z;
            W[(kq * 4 + 3) * 128 + cs] = w4[q].w;
        }
#pragma unroll
        for (int t = 0; t < 4; t++) {
            int k = rg + 8 * t;
            unsigned long long d;
            DUP2(d, hv[t]);
            H[k * 32 + slot] = d;
        }
        __syncthreads();
        // prefetch next chunk
        if (kc < 7) {
#pragma unroll
            for (int q = 0; q < 4; q++) {
                int F = tid + 256 * q;
                int kq = F & 7, vcol = F >> 3;
                int v = vbase + vcol; if (v >= VOCAB) v = VOCAB - 1;
                w4[q] = *(const float4*)(W_dec + v * 256 + (kc + 1) * 32 + kq * 4);
            }
#pragma unroll
            for (int t = 0; t < 4; t++) {
                int k = rg + 8 * t;
                hv[t] = __ldcg(g_Ht + ((kc + 1) * 32 + k) * HT_STRIDE + rbase + cslot);
            }
        }
        // compute: 11 issue slots per kk for 32 MACs
#pragma unroll
        for (int kk = 0; kk < 32; kk++) {
            ulonglong2 wu = *(const ulonglong2*)(W + kk * 128 + ((vg ^ (kk >> 2)) << 2));
            const ulonglong2* hp = (const ulonglong2*)(H + kk * 32 + rg * 4);
            ulonglong2 h01 = hp[0];
            ulonglong2 h23 = hp[1];
            FMA2(acc[0][0], h01.x, wu.x); FMA2(acc[0][1], h01.x, wu.y);
            FMA2(acc[1][0], h01.y, wu.x); FMA2(acc[1][1], h01.y, wu.y);
            FMA2(acc[2][0], h23.x, wu.x); FMA2(acc[2][1], h23.x, wu.y);
            FMA2(acc[3][0], h23.y, wu.x); FMA2(acc[3][1], h23.y, wu.y);
        }
    }

    if (v0 < VOCAB) {
        float4 bv = *(const float4*)(b_dec + v0);
#pragma unroll
        for (int r = 0; r < 4; r++) {
            int lrow = rg * 4 + r;
            if (lrow < nrows) {
                float a0, a1, a2, a3;
                UNPACK64(a0, a1, acc[r][0]);
                UNPACK64(a2, a3, acc[r][1]);
                float4 o;
                o.x = fmaxf(a0 + bv.x, 0.f);
                o.y = fmaxf(a1 + bv.y, 0.f);
                o.z = fmaxf(a2 + bv.z, 0.f);
                o.w = fmaxf(a3 + bv.w, 0.f);
                *(float4*)(out + (rbase + lrow) * VOCAB + v0) = o;
            }
        }
    }
}

// ---------------- launch ----------------
extern "C" void kernel_launch(void* const* d_in, const int* in_sizes, int n_in,
                              void* d_out, int out_size) {
    const float* board    = (const float*)d_in[0];
    const float* conv_w   = (const float*)d_in[1];
    const float* conv_b   = (const float*)d_in[2];
    const float* bn_gamma = (const float*)d_in[3];
    const float* bn_beta  = (const float*)d_in[4];
    const float* p        = (const float*)d_in[5];
    const float* W_lin    = (const float*)d_in[6];
    const float* b_lin    = (const float*)d_in[7];
    const float* W_ih     = (const float*)d_in[8];
    const float* b_ih     = (const float*)d_in[9];
    const float* W_hh     = (const float*)d_in[10];
    const float* b_hh     = (const float*)d_in[11];
    const float* W_dec    = (const float*)d_in[12];
    const float* b_dec    = (const float*)d_in[13];
    float* out = (float*)d_out;

    const int K2_PAD_SMEM = 184320;   // blocks decode co-residency on LSTM SMs
    const int K3_SMEM = 49152;        // 32KB W + 16KB H (double-buffered)
    cudaFuncSetAttribute(k2_lstm, cudaFuncAttributeMaxDynamicSharedMemorySize, K2_PAD_SMEM);
    cudaFuncSetAttribute(k3_decode, cudaFuncAttributeMaxDynamicSharedMemorySize, K3_SMEM);

    k0_precompute<<<96, 256>>>(W_lin);
    k1_prep<<<1, 512>>>(board, conv_w, conv_b, bn_gamma, bn_beta, p, b_lin);
    k2_lstm<<<8, 256, K2_PAD_SMEM>>>(W_ih, W_hh, b_ih, b_hh);

    // decode: programmatic dependent launch -> overlaps the recurrence
    cudaLaunchConfig_t cfg = {};
    cfg.gridDim = dim3(391, NY, 1);
    cfg.blockDim = dim3(256, 1, 1);
    cfg.dynamicSmemBytes = K3_SMEM;
    cfg.stream = 0;
    cudaLaunchAttribute at[1];
    at[0].id = cudaLaunchAttributeProgrammaticStreamSerialization;
    at[0].val.programmaticStreamSerializationAllowed = 1;
    cfg.attrs = at;
    cfg.numAttrs = 1;
    cudaLaunchKernelEx(&cfg, k3_decode, W_dec, b_dec, out);
}